// round 13
// baseline (speedup 1.0000x reference)
#include <cuda_runtime.h>

#define BB     16
#define CC     512
#define SS     1024
#define HEADS  8
#define DH     64
#define INNER  512     // HEADS*DH
#define N3     1536    // 3*INNER
#define ATT_SCALE 0.125f  // 64^-0.5

// Scratch (static device globals — allocation-free per harness rules)
__device__ float g_qkv[(size_t)BB * SS * N3];    // [b][s][h*192 + {q,k,v}]
__device__ float g_res[(size_t)BB * SS * INNER]; // [b][s][h*64+d]

// tf32 round-to-nearest (keeps value in a float container)
__device__ __forceinline__ float tf32r(float f) {
    unsigned u;
    asm("cvt.rna.tf32.f32 %0, %1;" : "=r"(u) : "f"(f));
    return __uint_as_float(u);
}
__device__ __forceinline__ float4 tf32r4(float4 v) {
    return make_float4(tf32r(v.x), tf32r(v.y), tf32r(v.z), tf32r(v.w));
}

// m16n8k8 tf32 MMA, fp32 accumulate (D == C)
__device__ __forceinline__ void mma_tf32(float* d, const float* a, const float* b) {
    asm volatile(
        "mma.sync.aligned.m16n8k8.row.col.f32.tf32.tf32.f32 "
        "{%0,%1,%2,%3}, {%4,%5,%6,%7}, {%8,%9}, {%0,%1,%2,%3};\n"
        : "+f"(d[0]), "+f"(d[1]), "+f"(d[2]), "+f"(d[3])
        : "r"(__float_as_uint(a[0])), "r"(__float_as_uint(a[1])),
          "r"(__float_as_uint(a[2])), "r"(__float_as_uint(a[3])),
          "r"(__float_as_uint(b[0])), "r"(__float_as_uint(b[1])));
}

// ---- fragment-permuted smem layouts ----
#define AGSZ 136
#define BGSZ 72
// GEMM A (k 0..15, m 0..127): group (k>>3)*8 + (m>>4)
__device__ __forceinline__ int idxA(int k, int m) {
    return (((k >> 3) * 8) + (m >> 4)) * AGSZ
         + (((m & 7) << 2) + (k & 3)) * 4 + (((k >> 2) & 1) << 1) + ((m >> 3) & 1);
}
// GEMM B (k 0..15, n 0..127): group (k>>3)*16 + (n>>3)
__device__ __forceinline__ int idxB(int k, int n) {
    return (((k >> 3) * 16) + (n >> 3)) * BGSZ
         + ((((n & 7) << 2) + (k & 3)) << 1) + ((k >> 2) & 1);
}

// ---------------------------------------------------------------------------
// Kernel 1: qkv = xs @ W_proj + b_proj, tf32 mma.sync, frag-permuted smem.
// (unchanged from R9)
// ---------------------------------------------------------------------------
__global__ __launch_bounds__(256, 2) void qkv_gemm_k(
    const float* __restrict__ x, const float* __restrict__ Wp,
    const float* __restrict__ bp)
{
    __shared__ float sAp[2][16 * AGSZ];
    __shared__ float sBp[2][32 * BGSZ];
    const int n0 = blockIdx.x * 128;
    const int m0 = blockIdx.y * 128;
    const int b  = m0 >> 10;
    const int s0 = m0 & (SS - 1);
    const int tid = threadIdx.x;
    const int lk = tid >> 4, lm4 = (tid & 15) << 2;
    const int warp = tid >> 5, lane = tid & 31;
    const int wm = warp & 1, wn = warp >> 1;
    const int gid = lane >> 2, tig = lane & 3;

    float4 av0, av1, bv0, bv1;
    {
        const size_t arow = ((size_t)(b * CC + lk)) * SS + s0 + lm4;
        const size_t brow = (size_t)lk * N3 + n0 + lm4;
        av0 = *(const float4*)&x[arow];
        av1 = *(const float4*)&x[arow + 64];
        bv0 = *(const float4*)&Wp[brow];
        bv1 = *(const float4*)&Wp[brow + 64];
    }
    {
        float a0[4] = {av0.x, av0.y, av0.z, av0.w};
        float a1[4] = {av1.x, av1.y, av1.z, av1.w};
        float b0[4] = {bv0.x, bv0.y, bv0.z, bv0.w};
        float b1[4] = {bv1.x, bv1.y, bv1.z, bv1.w};
        #pragma unroll
        for (int j = 0; j < 4; j++) {
            sAp[0][idxA(lk, lm4 + j)]      = tf32r(a0[j]);
            sAp[0][idxA(lk, lm4 + 64 + j)] = tf32r(a1[j]);
            sBp[0][idxB(lk, lm4 + j)]      = tf32r(b0[j]);
            sBp[0][idxB(lk, lm4 + 64 + j)] = tf32r(b1[j]);
        }
    }
    __syncthreads();

    float acc[4][4][4] = {};

    for (int k0 = 0; k0 < CC; k0 += 16) {
        const int buf = (k0 >> 4) & 1;
        const bool more = (k0 + 16) < CC;
        if (more) {
            const size_t arow = ((size_t)(b * CC + k0 + 16 + lk)) * SS + s0 + lm4;
            const size_t brow = (size_t)(k0 + 16 + lk) * N3 + n0 + lm4;
            av0 = *(const float4*)&x[arow];
            av1 = *(const float4*)&x[arow + 64];
            bv0 = *(const float4*)&Wp[brow];
            bv1 = *(const float4*)&Wp[brow + 64];
        }
        #pragma unroll
        for (int ks8 = 0; ks8 < 2; ks8++) {
            float4 afr[4];
            float2 bfr[4];
            #pragma unroll
            for (int mf = 0; mf < 4; mf++)
                afr[mf] = *(const float4*)&sAp[buf][(ks8 * 8 + wm * 4 + mf) * AGSZ + lane * 4];
            #pragma unroll
            for (int nf = 0; nf < 4; nf++)
                bfr[nf] = *(const float2*)&sBp[buf][(ks8 * 16 + wn * 4 + nf) * BGSZ + lane * 2];
            #pragma unroll
            for (int mf = 0; mf < 4; mf++)
                #pragma unroll
                for (int nf = 0; nf < 4; nf++)
                    mma_tf32(acc[mf][nf], (const float*)&afr[mf], (const float*)&bfr[nf]);
        }
        if (more) {
            const int nb = buf ^ 1;
            float a0[4] = {av0.x, av0.y, av0.z, av0.w};
            float a1[4] = {av1.x, av1.y, av1.z, av1.w};
            float b0[4] = {bv0.x, bv0.y, bv0.z, bv0.w};
            float b1[4] = {bv1.x, bv1.y, bv1.z, bv1.w};
            #pragma unroll
            for (int j = 0; j < 4; j++) {
                sAp[nb][idxA(lk, lm4 + j)]      = tf32r(a0[j]);
                sAp[nb][idxA(lk, lm4 + 64 + j)] = tf32r(a1[j]);
                sBp[nb][idxB(lk, lm4 + j)]      = tf32r(b0[j]);
                sBp[nb][idxB(lk, lm4 + 64 + j)] = tf32r(b1[j]);
            }
            __syncthreads();
        }
    }

    #pragma unroll
    for (int mf = 0; mf < 4; mf++) {
        const int rowa = m0 + wm * 64 + mf * 16 + gid;
        const int rowb = rowa + 8;
        #pragma unroll
        for (int nf = 0; nf < 4; nf++) {
            const int col = n0 + wn * 32 + nf * 8 + tig * 2;
            const float2 bias = *(const float2*)&bp[col];
            float2 oa = make_float2(acc[mf][nf][0] + bias.x, acc[mf][nf][1] + bias.y);
            float2 ob = make_float2(acc[mf][nf][2] + bias.x, acc[mf][nf][3] + bias.y);
            *(float2*)&g_qkv[(size_t)rowa * N3 + col] = oa;
            *(float2*)&g_qkv[(size_t)rowb * N3 + col] = ob;
        }
    }
}

// ---------------------------------------------------------------------------
// Kernel 2: flash attention, tf32 mma.sync, ALL tiles frag-permuted.
//   sQp: A-layout (q rows, k=d),  group (q>>4)*8 + (d>>3)   8704 floats
//   sKp: B-layout (n=j,  k=d),    group (j>>3)*8 + (d>>3)   4608
//   sVp: B-layout (n=dh, k=j),    group (j>>3)*8 + (dh>>3)  4608
//   sPp: A-layout (q rows, k=j),  group (q>>4)*8 + (j>>3)   8704
// ---------------------------------------------------------------------------
__global__ __launch_bounds__(256, 2) void attn_k()
{
    extern __shared__ float sm[];
    float* sQp = sm;
    float* sKp = sQp + 8704;
    float* sVp = sKp + 4608;
    float* sPp = sVp + 4608;

    const int bh = blockIdx.y;
    const int b = bh >> 3, h = bh & 7;
    const int q0 = blockIdx.x * 128;
    const int tid = threadIdx.x;
    const int warp = tid >> 5, lane = tid & 31;
    const int gid = lane >> 2, tig = lane & 3;
    const int qw = warp * 16;

    const float* qbase = g_qkv + (size_t)b * SS * N3 + h * (3 * DH);

    // ---- Q load: scale + tf32 + permuted A-layout store ----
    #pragma unroll
    for (int it = 0; it < 8; it++) {
        int idx = tid + it * 256;
        int i = idx >> 4, d4 = (idx & 15) << 2;
        float4 v = *(const float4*)&qbase[(size_t)(q0 + i) * N3 + d4];
        float vv[4] = {v.x, v.y, v.z, v.w};
        #pragma unroll
        for (int jj = 0; jj < 4; jj++) {
            int d = d4 + jj;
            sQp[((i >> 4) * 8 + (d >> 3)) * AGSZ
                + (((i & 7) << 2) + (d & 3)) * 4 + (((d >> 2) & 1) << 1) + ((i >> 3) & 1)]
                = tf32r(vv[jj] * ATT_SCALE);
        }
    }

    float m_i0 = -1e30f, m_i1 = -1e30f, l_i0 = 0.f, l_i1 = 0.f;
    float o[8][4] = {};

    // Prefetch kt=0 K/V
    float4 kreg[4], vreg[4];
    #pragma unroll
    for (int it = 0; it < 4; it++) {
        int idx = tid + it * 256;
        int j = idx >> 4, c4 = (idx & 15) << 2;
        const float* row = &qbase[(size_t)j * N3];
        kreg[it] = *(const float4*)&row[DH + c4];
        vreg[it] = *(const float4*)&row[2 * DH + c4];
    }

    // P-store base inner offset (constant per thread)
    const int pinner = (gid * 4 + ((tig << 1) & 3)) * 4 + ((tig >> 1) << 1);

    for (int kt = 0; kt < 16; kt++) {
        __syncthreads();   // prev tile's reads of sKp/sVp done (Q store @kt0)
        #pragma unroll
        for (int it = 0; it < 4; it++) {
            int idx = tid + it * 256;
            int j = idx >> 4, c4 = (idx & 15) << 2;
            float kk[4] = {kreg[it].x, kreg[it].y, kreg[it].z, kreg[it].w};
            float vv[4] = {vreg[it].x, vreg[it].y, vreg[it].z, vreg[it].w};
            const int jg = (j >> 3) * 8;
            #pragma unroll
            for (int jj = 0; jj < 4; jj++) {
                int d = c4 + jj;
                // K element (n=j, k=d)
                sKp[(jg + (d >> 3)) * BGSZ
                    + (((j & 7) << 2) + (d & 3)) * 2 + ((d >> 2) & 1)] = tf32r(kk[jj]);
                // V element (n=d(head dim), k=j)
                sVp[(jg + (d >> 3)) * BGSZ
                    + (((d & 7) << 2) + (j & 3)) * 2 + ((j >> 2) & 1)] = tf32r(vv[jj]);
            }
        }
        __syncthreads();

        if (kt + 1 < 16) {
            const int k0n = (kt + 1) * 64;
            #pragma unroll
            for (int it = 0; it < 4; it++) {
                int idx = tid + it * 256;
                int j = idx >> 4, c4 = (idx & 15) << 2;
                const float* row = &qbase[(size_t)(k0n + j) * N3];
                kreg[it] = *(const float4*)&row[DH + c4];
                vreg[it] = *(const float4*)&row[2 * DH + c4];
            }
        }

        // ---- S = Q K^T : vectorized fragment loads ----
        float sf[8][4] = {};
        #pragma unroll
        for (int ks8 = 0; ks8 < 8; ks8++) {
            float4 af = *(const float4*)&sQp[(warp * 8 + ks8) * AGSZ + lane * 4];
            #pragma unroll
            for (int nf = 0; nf < 8; nf++) {
                float2 bf = *(const float2*)&sKp[(nf * 8 + ks8) * BGSZ + lane * 2];
                mma_tf32(sf[nf], (const float*)&af, (const float*)&bf);
            }
        }

        // ---- online softmax: thread owns rows qw+gid, qw+gid+8 ----
        {
            float mx0 = -1e30f, mx1 = -1e30f;
            #pragma unroll
            for (int nf = 0; nf < 8; nf++) {
                mx0 = fmaxf(mx0, fmaxf(sf[nf][0], sf[nf][1]));
                mx1 = fmaxf(mx1, fmaxf(sf[nf][2], sf[nf][3]));
            }
            mx0 = fmaxf(mx0, __shfl_xor_sync(0xffffffffu, mx0, 1));
            mx0 = fmaxf(mx0, __shfl_xor_sync(0xffffffffu, mx0, 2));
            mx1 = fmaxf(mx1, __shfl_xor_sync(0xffffffffu, mx1, 1));
            mx1 = fmaxf(mx1, __shfl_xor_sync(0xffffffffu, mx1, 2));
            float mn0 = fmaxf(m_i0, mx0);
            float mn1 = fmaxf(m_i1, mx1);
            float rs0 = 0.f, rs1 = 0.f;
            #pragma unroll
            for (int nf = 0; nf < 8; nf++) {
                float e00 = __expf(sf[nf][0] - mn0);
                float e01 = __expf(sf[nf][1] - mn0);
                float e10 = __expf(sf[nf][2] - mn1);
                float e11 = __expf(sf[nf][3] - mn1);
                rs0 += e00 + e01;
                rs1 += e10 + e11;
                float* dst = &sPp[(warp * 8 + nf) * AGSZ + pinner];
                *(float2*)&dst[0] = make_float2(tf32r(e00), tf32r(e10));
                *(float2*)&dst[4] = make_float2(tf32r(e01), tf32r(e11));
            }
            rs0 += __shfl_xor_sync(0xffffffffu, rs0, 1);
            rs0 += __shfl_xor_sync(0xffffffffu, rs0, 2);
            rs1 += __shfl_xor_sync(0xffffffffu, rs1, 1);
            rs1 += __shfl_xor_sync(0xffffffffu, rs1, 2);
            float a0 = __expf(m_i0 - mn0);
            float a1 = __expf(m_i1 - mn1);
            l_i0 = l_i0 * a0 + rs0;  m_i0 = mn0;
            l_i1 = l_i1 * a1 + rs1;  m_i1 = mn1;
            #pragma unroll
            for (int nf = 0; nf < 8; nf++) {
                o[nf][0] *= a0; o[nf][1] *= a0;
                o[nf][2] *= a1; o[nf][3] *= a1;
            }
        }
        __syncwarp();   // sPp groups are per-warp private

        // ---- O += P V : vectorized fragment loads ----
        #pragma unroll
        for (int ks8 = 0; ks8 < 8; ks8++) {
            float4 af = *(const float4*)&sPp[(warp * 8 + ks8) * AGSZ + lane * 4];
            #pragma unroll
            for (int nf = 0; nf < 8; nf++) {
                float2 bf = *(const float2*)&sVp[(ks8 * 8 + nf) * BGSZ + lane * 2];
                mma_tf32(o[nf], (const float*)&af, (const float*)&bf);
            }
        }
    }

    const float inv0 = 1.f / l_i0;
    const float inv1 = 1.f / l_i1;
    float* rbase = g_res + ((size_t)b * SS + q0) * INNER + h * DH;
    #pragma unroll
    for (int nf = 0; nf < 8; nf++) {
        const int col = nf * 8 + 2 * tig;
        *(float2*)&rbase[(size_t)(qw + gid) * INNER + col] =
            make_float2(o[nf][0] * inv0, o[nf][1] * inv0);
        *(float2*)&rbase[(size_t)(qw + gid + 8) * INNER + col] =
            make_float2(o[nf][2] * inv1, o[nf][3] * inv1);
    }
}

// ---------------------------------------------------------------------------
// Kernel 3: out = res @ W_out + b_out + x, tf32 mma.sync, frag-permuted smem.
// (unchanged from R9)
// ---------------------------------------------------------------------------
__global__ __launch_bounds__(256, 2) void out_gemm_k(
    const float* __restrict__ x, const float* __restrict__ Wo,
    const float* __restrict__ bo, float* __restrict__ out)
{
    __shared__ float sAp[2][16 * AGSZ];
    __shared__ float sBp[2][32 * BGSZ];
    const int s0 = blockIdx.x * 128;
    const int c0 = blockIdx.y * 128;
    const int b  = blockIdx.z;
    const int tid = threadIdx.x;
    const int lk = tid >> 4, lc4 = (tid & 15) << 2;
    const int ls = tid >> 1, lkb = (tid & 1) << 3;
    const int warp = tid >> 5, lane = tid & 31;
    const int wm = warp & 1, wn = warp >> 1;
    const int gid = lane >> 2, tig = lane & 3;

    float4 av0, av1, bv0, bv1;
    {
        const size_t arow = (size_t)lk * CC + c0 + lc4;
        av0 = *(const float4*)&Wo[arow];
        av1 = *(const float4*)&Wo[arow + 64];
        const size_t brow = ((size_t)(b * SS + s0 + ls)) * INNER + lkb;
        bv0 = *(const float4*)&g_res[brow];
        bv1 = *(const float4*)&g_res[brow + 4];
    }
    {
        float a0[4] = {av0.x, av0.y, av0.z, av0.w};
        float a1[4] = {av1.x, av1.y, av1.z, av1.w};
        float b0[4] = {bv0.x, bv0.y, bv0.z, bv0.w};
        float b1[4] = {bv1.x, bv1.y, bv1.z, bv1.w};
        #pragma unroll
        for (int j = 0; j < 4; j++) {
            sAp[0][idxA(lk, lc4 + j)]      = tf32r(a0[j]);
            sAp[0][idxA(lk, lc4 + 64 + j)] = tf32r(a1[j]);
            sBp[0][idxB(lkb + j, ls)]      = tf32r(b0[j]);
            sBp[0][idxB(lkb + 4 + j, ls)]  = tf32r(b1[j]);
        }
    }
    __syncthreads();

    float acc[4][4][4] = {};

    for (int k0 = 0; k0 < INNER; k0 += 16) {
        const int buf = (k0 >> 4) & 1;
        const bool more = (k0 + 16) < INNER;
        if (more) {
            const size_t arow = (size_t)(k0 + 16 + lk) * CC + c0 + lc4;
            av0 = *(const float4*)&Wo[arow];
            av1 = *(const float4*)&Wo[arow + 64];
            const size_t brow = ((size_t)(b * SS + s0 + ls)) * INNER + k0 + 16 + lkb;
            bv0 = *(const float4*)&g_res[brow];
            bv1 = *(const float4*)&g_res[brow + 4];
        }
        #pragma unroll
        for (int ks8 = 0; ks8 < 2; ks8++) {
            float4 afr[4];
            float2 bfr[4];
            #pragma unroll
            for (int mf = 0; mf < 4; mf++)
                afr[mf] = *(const float4*)&sAp[buf][(ks8 * 8 + wm * 4 + mf) * AGSZ + lane * 4];
            #pragma unroll
            for (int nf = 0; nf < 4; nf++)
                bfr[nf] = *(const float2*)&sBp[buf][(ks8 * 16 + wn * 4 + nf) * BGSZ + lane * 2];
            #pragma unroll
            for (int mf = 0; mf < 4; mf++)
                #pragma unroll
                for (int nf = 0; nf < 4; nf++)
                    mma_tf32(acc[mf][nf], (const float*)&afr[mf], (const float*)&bfr[nf]);
        }
        if (more) {
            const int nb = buf ^ 1;
            float a0[4] = {av0.x, av0.y, av0.z, av0.w};
            float a1[4] = {av1.x, av1.y, av1.z, av1.w};
            float b0[4] = {bv0.x, bv0.y, bv0.z, bv0.w};
            float b1[4] = {bv1.x, bv1.y, bv1.z, bv1.w};
            #pragma unroll
            for (int j = 0; j < 4; j++) {
                sAp[nb][idxA(lk, lc4 + j)]      = tf32r(a0[j]);
                sAp[nb][idxA(lk, lc4 + 64 + j)] = tf32r(a1[j]);
                sBp[nb][idxB(lkb + j, ls)]      = tf32r(b0[j]);
                sBp[nb][idxB(lkb + 4 + j, ls)]  = tf32r(b1[j]);
            }
            __syncthreads();
        }
    }

    #pragma unroll
    for (int mf = 0; mf < 4; mf++) {
        const int ca = c0 + wm * 64 + mf * 16 + gid;
        const int cb = ca + 8;
        const float biasa = bo[ca];
        const float biasb = bo[cb];
        #pragma unroll
        for (int nf = 0; nf < 4; nf++) {
            const int s = s0 + wn * 32 + nf * 8 + tig * 2;
            const size_t basea = ((size_t)(b * CC + ca)) * SS + s;
            const size_t baseb = ((size_t)(b * CC + cb)) * SS + s;
            float2 xva = *(const float2*)&x[basea];
            float2 xvb = *(const float2*)&x[baseb];
            float2 oa = make_float2(acc[mf][nf][0] + biasa + xva.x,
                                    acc[mf][nf][1] + biasa + xva.y);
            float2 ob = make_float2(acc[mf][nf][2] + biasb + xvb.x,
                                    acc[mf][nf][3] + biasb + xvb.y);
            *(float2*)&out[basea] = oa;
            *(float2*)&out[baseb] = ob;
        }
    }
}

// ---------------------------------------------------------------------------
extern "C" void kernel_launch(void* const* d_in, const int* in_sizes, int n_in,
                              void* d_out, int out_size)
{
    const float* x  = (const float*)d_in[0];
    const float* Wp = (const float*)d_in[1];
    const float* bp = (const float*)d_in[2];
    const float* Wo = (const float*)d_in[3];
    const float* bo = (const float*)d_in[4];
    float* out = (float*)d_out;

    const int attn_smem = (8704 + 4608 + 4608 + 8704) * (int)sizeof(float); // 106496
    cudaFuncSetAttribute(attn_k, cudaFuncAttributeMaxDynamicSharedMemorySize,
                         attn_smem);

    dim3 g1(N3 / 128, (BB * SS) / 128);        // 12 x 128
    qkv_gemm_k<<<g1, 256>>>(x, Wp, bp);

    dim3 g2(SS / 128, BB * HEADS);             // 8 x 128
    attn_k<<<g2, 256, attn_smem>>>();

    dim3 g3(SS / 128, CC / 128, BB);           // 8 x 4 x 16
    out_gemm_k<<<g3, 256>>>(x, Wo, bo, out);
}

// round 15
// speedup vs baseline: 1.5541x; 1.5541x over previous
#include <cuda_runtime.h>

#define BB     16
#define CC     512
#define SS     1024
#define HEADS  8
#define DH     64
#define INNER  512     // HEADS*DH
#define N3     1536    // 3*INNER
#define ATT_SCALE 0.125f  // 64^-0.5
#define STR    72      // attn smem row stride (72 mod 32 == 8)

// Scratch (static device globals — allocation-free per harness rules)
__device__ float g_qkv[(size_t)BB * SS * N3];    // [b][s][h*192 + {q,k,v}]
__device__ float g_res[(size_t)BB * SS * INNER]; // [b][s][h*64+d]

// tf32 round-to-nearest (kept only where rounding matters: attn P store)
__device__ __forceinline__ float tf32r(float f) {
    unsigned u;
    asm("cvt.rna.tf32.f32 %0, %1;" : "=r"(u) : "f"(f));
    return __uint_as_float(u);
}

// m16n8k8 tf32 MMA, fp32 accumulate (D == C). Raw fp32 operands are
// truncated to tf32 by the tensor core.
__device__ __forceinline__ void mma_tf32(float* d, const float* a, const float* b) {
    asm volatile(
        "mma.sync.aligned.m16n8k8.row.col.f32.tf32.tf32.f32 "
        "{%0,%1,%2,%3}, {%4,%5,%6,%7}, {%8,%9}, {%0,%1,%2,%3};\n"
        : "+f"(d[0]), "+f"(d[1]), "+f"(d[2]), "+f"(d[3])
        : "r"(__float_as_uint(a[0])), "r"(__float_as_uint(a[1])),
          "r"(__float_as_uint(a[2])), "r"(__float_as_uint(a[3])),
          "r"(__float_as_uint(b[0])), "r"(__float_as_uint(b[1])));
}

// ---- fragment-permuted smem layouts (GEMM kernels) ----
#define AGSZ 136
#define BGSZ 72
__device__ __forceinline__ int idxA(int k, int m) {
    return (((k >> 3) * 8) + (m >> 4)) * AGSZ
         + (((m & 7) << 2) + (k & 3)) * 4 + (((k >> 2) & 1) << 1) + ((m >> 3) & 1);
}
__device__ __forceinline__ int idxB(int k, int n) {
    return (((k >> 3) * 16) + (n >> 3)) * BGSZ
         + ((((n & 7) << 2) + (k & 3)) << 1) + ((k >> 2) & 1);
}

// ---------------------------------------------------------------------------
// Kernel 1: qkv = xs @ W_proj + b_proj, tf32 mma.sync, frag-permuted smem.
// Raw fp32 in smem (HW tf32 truncation), no cvt ops.
// ---------------------------------------------------------------------------
__global__ __launch_bounds__(256, 2) void qkv_gemm_k(
    const float* __restrict__ x, const float* __restrict__ Wp,
    const float* __restrict__ bp)
{
    __shared__ float sAp[2][16 * AGSZ];
    __shared__ float sBp[2][32 * BGSZ];
    const int n0 = blockIdx.x * 128;
    const int m0 = blockIdx.y * 128;
    const int b  = m0 >> 10;
    const int s0 = m0 & (SS - 1);
    const int tid = threadIdx.x;
    const int lk = tid >> 4, lm4 = (tid & 15) << 2;
    const int warp = tid >> 5, lane = tid & 31;
    const int wm = warp & 1, wn = warp >> 1;
    const int gid = lane >> 2, tig = lane & 3;

    float4 av0, av1, bv0, bv1;
    {
        const size_t arow = ((size_t)(b * CC + lk)) * SS + s0 + lm4;
        const size_t brow = (size_t)lk * N3 + n0 + lm4;
        av0 = *(const float4*)&x[arow];
        av1 = *(const float4*)&x[arow + 64];
        bv0 = *(const float4*)&Wp[brow];
        bv1 = *(const float4*)&Wp[brow + 64];
    }
    {
        float a0[4] = {av0.x, av0.y, av0.z, av0.w};
        float a1[4] = {av1.x, av1.y, av1.z, av1.w};
        float b0[4] = {bv0.x, bv0.y, bv0.z, bv0.w};
        float b1[4] = {bv1.x, bv1.y, bv1.z, bv1.w};
        #pragma unroll
        for (int j = 0; j < 4; j++) {
            sAp[0][idxA(lk, lm4 + j)]      = a0[j];
            sAp[0][idxA(lk, lm4 + 64 + j)] = a1[j];
            sBp[0][idxB(lk, lm4 + j)]      = b0[j];
            sBp[0][idxB(lk, lm4 + 64 + j)] = b1[j];
        }
    }
    __syncthreads();

    float acc[4][4][4] = {};

    for (int k0 = 0; k0 < CC; k0 += 16) {
        const int buf = (k0 >> 4) & 1;
        const bool more = (k0 + 16) < CC;
        if (more) {
            const size_t arow = ((size_t)(b * CC + k0 + 16 + lk)) * SS + s0 + lm4;
            const size_t brow = (size_t)(k0 + 16 + lk) * N3 + n0 + lm4;
            av0 = *(const float4*)&x[arow];
            av1 = *(const float4*)&x[arow + 64];
            bv0 = *(const float4*)&Wp[brow];
            bv1 = *(const float4*)&Wp[brow + 64];
        }
        #pragma unroll
        for (int ks8 = 0; ks8 < 2; ks8++) {
            float4 afr[4];
            float2 bfr[4];
            #pragma unroll
            for (int mf = 0; mf < 4; mf++)
                afr[mf] = *(const float4*)&sAp[buf][(ks8 * 8 + wm * 4 + mf) * AGSZ + lane * 4];
            #pragma unroll
            for (int nf = 0; nf < 4; nf++)
                bfr[nf] = *(const float2*)&sBp[buf][(ks8 * 16 + wn * 4 + nf) * BGSZ + lane * 2];
            #pragma unroll
            for (int mf = 0; mf < 4; mf++)
                #pragma unroll
                for (int nf = 0; nf < 4; nf++)
                    mma_tf32(acc[mf][nf], (const float*)&afr[mf], (const float*)&bfr[nf]);
        }
        if (more) {
            const int nb = buf ^ 1;
            float a0[4] = {av0.x, av0.y, av0.z, av0.w};
            float a1[4] = {av1.x, av1.y, av1.z, av1.w};
            float b0[4] = {bv0.x, bv0.y, bv0.z, bv0.w};
            float b1[4] = {bv1.x, bv1.y, bv1.z, bv1.w};
            #pragma unroll
            for (int j = 0; j < 4; j++) {
                sAp[nb][idxA(lk, lm4 + j)]      = a0[j];
                sAp[nb][idxA(lk, lm4 + 64 + j)] = a1[j];
                sBp[nb][idxB(lk, lm4 + j)]      = b0[j];
                sBp[nb][idxB(lk, lm4 + 64 + j)] = b1[j];
            }
            __syncthreads();
        }
    }

    #pragma unroll
    for (int mf = 0; mf < 4; mf++) {
        const int rowa = m0 + wm * 64 + mf * 16 + gid;
        const int rowb = rowa + 8;
        #pragma unroll
        for (int nf = 0; nf < 4; nf++) {
            const int col = n0 + wn * 32 + nf * 8 + tig * 2;
            const float2 bias = *(const float2*)&bp[col];
            float2 oa = make_float2(acc[mf][nf][0] + bias.x, acc[mf][nf][1] + bias.y);
            float2 ob = make_float2(acc[mf][nf][2] + bias.x, acc[mf][nf][3] + bias.y);
            *(float2*)&g_qkv[(size_t)rowa * N3 + col] = oa;
            *(float2*)&g_qkv[(size_t)rowb * N3 + col] = ob;
        }
    }
}

// ---------------------------------------------------------------------------
// Kernel 2: flash attention, tf32 mma.sync, natural smem layouts (R9 version),
// raw fp32 Q/K/V in smem (HW truncation); explicit tf32 rounding on P only.
// ---------------------------------------------------------------------------
__global__ __launch_bounds__(256, 2) void attn_k()
{
    extern __shared__ float sm[];
    float* sQ = sm;                 // [128][72]  (scaled)
    float* sK = sQ + 128 * STR;     // [64][72]
    float* sV = sK + 64 * STR;      // [64][72]
    float* sP = sV + 64 * STR;      // [128][72]  (tf32-rounded)

    const int bh = blockIdx.y;
    const int b = bh >> 3, h = bh & 7;
    const int q0 = blockIdx.x * 128;
    const int tid = threadIdx.x;
    const int warp = tid >> 5, lane = tid & 31;
    const int gid = lane >> 2, tig = lane & 3;
    const int qw = warp * 16;

    const float* qbase = g_qkv + (size_t)b * SS * N3 + h * (3 * DH);

    #pragma unroll
    for (int it = 0; it < 8; it++) {
        int idx = tid + it * 256;
        int i = idx >> 4, d4 = (idx & 15) << 2;
        float4 v = *(const float4*)&qbase[(size_t)(q0 + i) * N3 + d4];
        v.x *= ATT_SCALE; v.y *= ATT_SCALE; v.z *= ATT_SCALE; v.w *= ATT_SCALE;
        *(float4*)&sQ[i * STR + d4] = v;
    }

    float m_i0 = -1e30f, m_i1 = -1e30f, l_i0 = 0.f, l_i1 = 0.f;
    float o[8][4] = {};

    float4 kreg[4], vreg[4];
    #pragma unroll
    for (int it = 0; it < 4; it++) {
        int idx = tid + it * 256;
        int j = idx >> 4, c4 = (idx & 15) << 2;
        const float* row = &qbase[(size_t)j * N3];
        kreg[it] = *(const float4*)&row[DH + c4];
        vreg[it] = *(const float4*)&row[2 * DH + c4];
    }

    for (int kt = 0; kt < 16; kt++) {
        __syncthreads();
        #pragma unroll
        for (int it = 0; it < 4; it++) {
            int idx = tid + it * 256;
            int j = idx >> 4, c4 = (idx & 15) << 2;
            *(float4*)&sK[j * STR + c4] = kreg[it];
            *(float4*)&sV[j * STR + c4] = vreg[it];
        }
        __syncthreads();

        if (kt + 1 < 16) {
            const int k0n = (kt + 1) * 64;
            #pragma unroll
            for (int it = 0; it < 4; it++) {
                int idx = tid + it * 256;
                int j = idx >> 4, c4 = (idx & 15) << 2;
                const float* row = &qbase[(size_t)(k0n + j) * N3];
                kreg[it] = *(const float4*)&row[DH + c4];
                vreg[it] = *(const float4*)&row[2 * DH + c4];
            }
        }

        float sf[8][4] = {};
        #pragma unroll
        for (int ks = 0; ks < 64; ks += 8) {
            float afr[4];
            afr[0] = sQ[(qw + gid) * STR + ks + tig];
            afr[1] = sQ[(qw + gid + 8) * STR + ks + tig];
            afr[2] = sQ[(qw + gid) * STR + ks + tig + 4];
            afr[3] = sQ[(qw + gid + 8) * STR + ks + tig + 4];
            #pragma unroll
            for (int nf = 0; nf < 8; nf++) {
                float bfr[2];
                bfr[0] = sK[(nf * 8 + gid) * STR + ks + tig];
                bfr[1] = sK[(nf * 8 + gid) * STR + ks + tig + 4];
                mma_tf32(sf[nf], afr, bfr);
            }
        }

        {
            float mx0 = -1e30f, mx1 = -1e30f;
            #pragma unroll
            for (int nf = 0; nf < 8; nf++) {
                mx0 = fmaxf(mx0, fmaxf(sf[nf][0], sf[nf][1]));
                mx1 = fmaxf(mx1, fmaxf(sf[nf][2], sf[nf][3]));
            }
            mx0 = fmaxf(mx0, __shfl_xor_sync(0xffffffffu, mx0, 1));
            mx0 = fmaxf(mx0, __shfl_xor_sync(0xffffffffu, mx0, 2));
            mx1 = fmaxf(mx1, __shfl_xor_sync(0xffffffffu, mx1, 1));
            mx1 = fmaxf(mx1, __shfl_xor_sync(0xffffffffu, mx1, 2));
            float mn0 = fmaxf(m_i0, mx0);
            float mn1 = fmaxf(m_i1, mx1);
            float rs0 = 0.f, rs1 = 0.f;
            float* p0 = &sP[(qw + gid) * STR + 2 * tig];
            float* p1 = &sP[(qw + gid + 8) * STR + 2 * tig];
            #pragma unroll
            for (int nf = 0; nf < 8; nf++) {
                float e00 = __expf(sf[nf][0] - mn0);
                float e01 = __expf(sf[nf][1] - mn0);
                float e10 = __expf(sf[nf][2] - mn1);
                float e11 = __expf(sf[nf][3] - mn1);
                rs0 += e00 + e01;
                rs1 += e10 + e11;
                *(float2*)&p0[nf * 8] = make_float2(tf32r(e00), tf32r(e01));
                *(float2*)&p1[nf * 8] = make_float2(tf32r(e10), tf32r(e11));
            }
            rs0 += __shfl_xor_sync(0xffffffffu, rs0, 1);
            rs0 += __shfl_xor_sync(0xffffffffu, rs0, 2);
            rs1 += __shfl_xor_sync(0xffffffffu, rs1, 1);
            rs1 += __shfl_xor_sync(0xffffffffu, rs1, 2);
            float a0 = __expf(m_i0 - mn0);
            float a1 = __expf(m_i1 - mn1);
            l_i0 = l_i0 * a0 + rs0;  m_i0 = mn0;
            l_i1 = l_i1 * a1 + rs1;  m_i1 = mn1;
            #pragma unroll
            for (int nf = 0; nf < 8; nf++) {
                o[nf][0] *= a0; o[nf][1] *= a0;
                o[nf][2] *= a1; o[nf][3] *= a1;
            }
        }
        __syncwarp();

        #pragma unroll
        for (int ks = 0; ks < 64; ks += 8) {
            float afr[4];
            afr[0] = sP[(qw + gid) * STR + ks + tig];
            afr[1] = sP[(qw + gid + 8) * STR + ks + tig];
            afr[2] = sP[(qw + gid) * STR + ks + tig + 4];
            afr[3] = sP[(qw + gid + 8) * STR + ks + tig + 4];
            #pragma unroll
            for (int nf = 0; nf < 8; nf++) {
                float bfr[2];
                bfr[0] = sV[(ks + tig) * STR + nf * 8 + gid];
                bfr[1] = sV[(ks + tig + 4) * STR + nf * 8 + gid];
                mma_tf32(o[nf], afr, bfr);
            }
        }
    }

    const float inv0 = 1.f / l_i0;
    const float inv1 = 1.f / l_i1;
    float* rbase = g_res + ((size_t)b * SS + q0) * INNER + h * DH;
    #pragma unroll
    for (int nf = 0; nf < 8; nf++) {
        const int col = nf * 8 + 2 * tig;
        *(float2*)&rbase[(size_t)(qw + gid) * INNER + col] =
            make_float2(o[nf][0] * inv0, o[nf][1] * inv0);
        *(float2*)&rbase[(size_t)(qw + gid + 8) * INNER + col] =
            make_float2(o[nf][2] * inv1, o[nf][3] * inv1);
    }
}

// ---------------------------------------------------------------------------
// Kernel 3: out = res @ W_out + b_out + x, tf32 mma.sync, frag-permuted smem,
// raw fp32 operands (HW truncation).
// ---------------------------------------------------------------------------
__global__ __launch_bounds__(256, 2) void out_gemm_k(
    const float* __restrict__ x, const float* __restrict__ Wo,
    const float* __restrict__ bo, float* __restrict__ out)
{
    __shared__ float sAp[2][16 * AGSZ];
    __shared__ float sBp[2][32 * BGSZ];
    const int s0 = blockIdx.x * 128;
    const int c0 = blockIdx.y * 128;
    const int b  = blockIdx.z;
    const int tid = threadIdx.x;
    const int lk = tid >> 4, lc4 = (tid & 15) << 2;
    const int ls = tid >> 1, lkb = (tid & 1) << 3;
    const int warp = tid >> 5, lane = tid & 31;
    const int wm = warp & 1, wn = warp >> 1;
    const int gid = lane >> 2, tig = lane & 3;

    float4 av0, av1, bv0, bv1;
    {
        const size_t arow = (size_t)lk * CC + c0 + lc4;
        av0 = *(const float4*)&Wo[arow];
        av1 = *(const float4*)&Wo[arow + 64];
        const size_t brow = ((size_t)(b * SS + s0 + ls)) * INNER + lkb;
        bv0 = *(const float4*)&g_res[brow];
        bv1 = *(const float4*)&g_res[brow + 4];
    }
    {
        float a0[4] = {av0.x, av0.y, av0.z, av0.w};
        float a1[4] = {av1.x, av1.y, av1.z, av1.w};
        float b0[4] = {bv0.x, bv0.y, bv0.z, bv0.w};
        float b1[4] = {bv1.x, bv1.y, bv1.z, bv1.w};
        #pragma unroll
        for (int j = 0; j < 4; j++) {
            sAp[0][idxA(lk, lc4 + j)]      = a0[j];
            sAp[0][idxA(lk, lc4 + 64 + j)] = a1[j];
            sBp[0][idxB(lkb + j, ls)]      = b0[j];
            sBp[0][idxB(lkb + 4 + j, ls)]  = b1[j];
        }
    }
    __syncthreads();

    float acc[4][4][4] = {};

    for (int k0 = 0; k0 < INNER; k0 += 16) {
        const int buf = (k0 >> 4) & 1;
        const bool more = (k0 + 16) < INNER;
        if (more) {
            const size_t arow = (size_t)(k0 + 16 + lk) * CC + c0 + lc4;
            av0 = *(const float4*)&Wo[arow];
            av1 = *(const float4*)&Wo[arow + 64];
            const size_t brow = ((size_t)(b * SS + s0 + ls)) * INNER + k0 + 16 + lkb;
            bv0 = *(const float4*)&g_res[brow];
            bv1 = *(const float4*)&g_res[brow + 4];
        }
        #pragma unroll
        for (int ks8 = 0; ks8 < 2; ks8++) {
            float4 afr[4];
            float2 bfr[4];
            #pragma unroll
            for (int mf = 0; mf < 4; mf++)
                afr[mf] = *(const float4*)&sAp[buf][(ks8 * 8 + wm * 4 + mf) * AGSZ + lane * 4];
            #pragma unroll
            for (int nf = 0; nf < 4; nf++)
                bfr[nf] = *(const float2*)&sBp[buf][(ks8 * 16 + wn * 4 + nf) * BGSZ + lane * 2];
            #pragma unroll
            for (int mf = 0; mf < 4; mf++)
                #pragma unroll
                for (int nf = 0; nf < 4; nf++)
                    mma_tf32(acc[mf][nf], (const float*)&afr[mf], (const float*)&bfr[nf]);
        }
        if (more) {
            const int nb = buf ^ 1;
            float a0[4] = {av0.x, av0.y, av0.z, av0.w};
            float a1[4] = {av1.x, av1.y, av1.z, av1.w};
            float b0[4] = {bv0.x, bv0.y, bv0.z, bv0.w};
            float b1[4] = {bv1.x, bv1.y, bv1.z, bv1.w};
            #pragma unroll
            for (int j = 0; j < 4; j++) {
                sAp[nb][idxA(lk, lc4 + j)]      = a0[j];
                sAp[nb][idxA(lk, lc4 + 64 + j)] = a1[j];
                sBp[nb][idxB(lkb + j, ls)]      = b0[j];
                sBp[nb][idxB(lkb + 4 + j, ls)]  = b1[j];
            }
            __syncthreads();
        }
    }

    #pragma unroll
    for (int mf = 0; mf < 4; mf++) {
        const int ca = c0 + wm * 64 + mf * 16 + gid;
        const int cb = ca + 8;
        const float biasa = bo[ca];
        const float biasb = bo[cb];
        #pragma unroll
        for (int nf = 0; nf < 4; nf++) {
            const int s = s0 + wn * 32 + nf * 8 + tig * 2;
            const size_t basea = ((size_t)(b * CC + ca)) * SS + s;
            const size_t baseb = ((size_t)(b * CC + cb)) * SS + s;
            float2 xva = *(const float2*)&x[basea];
            float2 xvb = *(const float2*)&x[baseb];
            float2 oa = make_float2(acc[mf][nf][0] + biasa + xva.x,
                                    acc[mf][nf][1] + biasa + xva.y);
            float2 ob = make_float2(acc[mf][nf][2] + biasb + xvb.x,
                                    acc[mf][nf][3] + biasb + xvb.y);
            *(float2*)&out[basea] = oa;
            *(float2*)&out[baseb] = ob;
        }
    }
}

// ---------------------------------------------------------------------------
extern "C" void kernel_launch(void* const* d_in, const int* in_sizes, int n_in,
                              void* d_out, int out_size)
{
    const float* x  = (const float*)d_in[0];
    const float* Wp = (const float*)d_in[1];
    const float* bp = (const float*)d_in[2];
    const float* Wo = (const float*)d_in[3];
    const float* bo = (const float*)d_in[4];
    float* out = (float*)d_out;

    const int attn_smem = (128 + 64 + 64 + 128) * STR * (int)sizeof(float); // 110592
    cudaFuncSetAttribute(attn_k, cudaFuncAttributeMaxDynamicSharedMemorySize,
                         attn_smem);

    dim3 g1(N3 / 128, (BB * SS) / 128);        // 12 x 128
    qkv_gemm_k<<<g1, 256>>>(x, Wp, bp);

    dim3 g2(SS / 128, BB * HEADS);             // 8 x 128
    attn_k<<<g2, 256, attn_smem>>>();

    dim3 g3(SS / 128, CC / 128, BB);           // 8 x 4 x 16
    out_gemm_k<<<g3, 256>>>(x, Wo, bo, out);
}

// round 16
// speedup vs baseline: 1.7130x; 1.1023x over previous
#include <cuda_runtime.h>
#include <cuda_bf16.h>

#define BB     16
#define CC     512
#define SS     1024
#define HEADS  8
#define DH     64
#define INNER  512     // HEADS*DH
#define N3     1536    // 3*INNER
#define ATT_SCALE 0.125f  // 64^-0.5
#define STR    72      // attn smem row stride (72 mod 32 == 8)
#define PITCH  12      // bf16 GEMM smem row pitch in b32 (conflict-free)

// Scratch (static device globals — allocation-free per harness rules)
__device__ float g_qkv[(size_t)BB * SS * N3];    // [b][s][h*192 + {q,k,v}]
__device__ float g_res[(size_t)BB * SS * INNER]; // [b][s][h*64+d]

// tf32 round-to-nearest
__device__ __forceinline__ float tf32r(float f) {
    unsigned u;
    asm("cvt.rna.tf32.f32 %0, %1;" : "=r"(u) : "f"(f));
    return __uint_as_float(u);
}
__device__ __forceinline__ float4 tf32r4(float4 v) {
    return make_float4(tf32r(v.x), tf32r(v.y), tf32r(v.z), tf32r(v.w));
}
// pack two fp32 -> bf16x2 (round-to-nearest): lo = first (lower k)
__device__ __forceinline__ unsigned bfpack(float lo, float hi) {
    unsigned d;
    asm("cvt.rn.bf16x2.f32 %0, %1, %2;" : "=r"(d) : "f"(hi), "f"(lo));
    return d;
}

// m16n8k8 tf32 MMA (attention)
__device__ __forceinline__ void mma_tf32(float* d, const float* a, const float* b) {
    asm volatile(
        "mma.sync.aligned.m16n8k8.row.col.f32.tf32.tf32.f32 "
        "{%0,%1,%2,%3}, {%4,%5,%6,%7}, {%8,%9}, {%0,%1,%2,%3};\n"
        : "+f"(d[0]), "+f"(d[1]), "+f"(d[2]), "+f"(d[3])
        : "r"(__float_as_uint(a[0])), "r"(__float_as_uint(a[1])),
          "r"(__float_as_uint(a[2])), "r"(__float_as_uint(a[3])),
          "r"(__float_as_uint(b[0])), "r"(__float_as_uint(b[1])));
}
// m16n8k16 bf16 MMA (projection GEMMs)
__device__ __forceinline__ void mma_bf16(float* d, const unsigned* a, const unsigned* b) {
    asm volatile(
        "mma.sync.aligned.m16n8k16.row.col.f32.bf16.bf16.f32 "
        "{%0,%1,%2,%3}, {%4,%5,%6,%7}, {%8,%9}, {%0,%1,%2,%3};\n"
        : "+f"(d[0]), "+f"(d[1]), "+f"(d[2]), "+f"(d[3])
        : "r"(a[0]), "r"(a[1]), "r"(a[2]), "r"(a[3]),
          "r"(b[0]), "r"(b[1]));
}

// ---------------------------------------------------------------------------
// Kernel 1: qkv = xs @ W_proj + b_proj.  bf16 m16n8k16, double-buffered.
// smem: sAh[m][kp] / sBh[n][kp], bf16x2 packs, pitch 12 b32.
// ---------------------------------------------------------------------------
__global__ __launch_bounds__(256, 2) void qkv_gemm_k(
    const float* __restrict__ x, const float* __restrict__ Wp,
    const float* __restrict__ bp)
{
    __shared__ unsigned sAh[2][128 * PITCH];
    __shared__ unsigned sBh[2][128 * PITCH];
    const int n0 = blockIdx.x * 128;
    const int m0 = blockIdx.y * 128;
    const int b  = m0 >> 10;
    const int s0 = m0 & (SS - 1);
    const int tid = threadIdx.x;
    const int warp = tid >> 5, lane = tid & 31;
    const int wm = warp & 1, wn = warp >> 1;
    const int gid = lane >> 2, tig = lane & 3;
    const int lr = tid & 127, hf = tid >> 7;   // loader: row lr, k-half hf

    float va[8], vb[8];
    // prologue: stage k0=0
    #pragma unroll
    for (int kk = 0; kk < 8; kk++) {
        const int krow = hf * 8 + kk;
        va[kk] = x[((size_t)(b * CC + krow)) * SS + s0 + lr];
        vb[kk] = Wp[(size_t)krow * N3 + n0 + lr];
    }
    {
        uint4 ua = make_uint4(bfpack(va[0], va[1]), bfpack(va[2], va[3]),
                              bfpack(va[4], va[5]), bfpack(va[6], va[7]));
        uint4 ub = make_uint4(bfpack(vb[0], vb[1]), bfpack(vb[2], vb[3]),
                              bfpack(vb[4], vb[5]), bfpack(vb[6], vb[7]));
        *(uint4*)&sAh[0][lr * PITCH + hf * 4] = ua;
        *(uint4*)&sBh[0][lr * PITCH + hf * 4] = ub;
    }
    __syncthreads();

    float acc[4][4][4] = {};

    for (int k0 = 0; k0 < CC; k0 += 16) {
        const int buf = (k0 >> 4) & 1;
        const bool more = (k0 + 16) < CC;
        if (more) {
            #pragma unroll
            for (int kk = 0; kk < 8; kk++) {
                const int krow = k0 + 16 + hf * 8 + kk;
                va[kk] = x[((size_t)(b * CC + krow)) * SS + s0 + lr];
                vb[kk] = Wp[(size_t)krow * N3 + n0 + lr];
            }
        }
        unsigned afr[4][4], bfr[4][2];
        #pragma unroll
        for (int mf = 0; mf < 4; mf++) {
            const int m = wm * 64 + mf * 16;
            afr[mf][0] = sAh[buf][(m + gid) * PITCH + tig];
            afr[mf][1] = sAh[buf][(m + gid + 8) * PITCH + tig];
            afr[mf][2] = sAh[buf][(m + gid) * PITCH + tig + 4];
            afr[mf][3] = sAh[buf][(m + gid + 8) * PITCH + tig + 4];
        }
        #pragma unroll
        for (int nf = 0; nf < 4; nf++) {
            const int n = wn * 32 + nf * 8;
            bfr[nf][0] = sBh[buf][(n + gid) * PITCH + tig];
            bfr[nf][1] = sBh[buf][(n + gid) * PITCH + tig + 4];
        }
        #pragma unroll
        for (int mf = 0; mf < 4; mf++)
            #pragma unroll
            for (int nf = 0; nf < 4; nf++)
                mma_bf16(acc[mf][nf], afr[mf], bfr[nf]);
        if (more) {
            const int nb = buf ^ 1;
            uint4 ua = make_uint4(bfpack(va[0], va[1]), bfpack(va[2], va[3]),
                                  bfpack(va[4], va[5]), bfpack(va[6], va[7]));
            uint4 ub = make_uint4(bfpack(vb[0], vb[1]), bfpack(vb[2], vb[3]),
                                  bfpack(vb[4], vb[5]), bfpack(vb[6], vb[7]));
            __syncthreads();
            *(uint4*)&sAh[nb][lr * PITCH + hf * 4] = ua;
            *(uint4*)&sBh[nb][lr * PITCH + hf * 4] = ub;
            __syncthreads();
        }
    }

    #pragma unroll
    for (int mf = 0; mf < 4; mf++) {
        const int rowa = m0 + wm * 64 + mf * 16 + gid;
        const int rowb = rowa + 8;
        #pragma unroll
        for (int nf = 0; nf < 4; nf++) {
            const int col = n0 + wn * 32 + nf * 8 + tig * 2;
            const float2 bias = *(const float2*)&bp[col];
            float2 oa = make_float2(acc[mf][nf][0] + bias.x, acc[mf][nf][1] + bias.y);
            float2 ob = make_float2(acc[mf][nf][2] + bias.x, acc[mf][nf][3] + bias.y);
            *(float2*)&g_qkv[(size_t)rowa * N3 + col] = oa;
            *(float2*)&g_qkv[(size_t)rowb * N3 + col] = ob;
        }
    }
}

// ---------------------------------------------------------------------------
// Kernel 2: flash attention, tf32 mma.sync (R15 structure), tf32 ROUNDING
// restored on Q/K/V/P smem stores.
// ---------------------------------------------------------------------------
__global__ __launch_bounds__(256, 2) void attn_k()
{
    extern __shared__ float sm[];
    float* sQ = sm;                 // [128][72]
    float* sK = sQ + 128 * STR;     // [64][72]
    float* sV = sK + 64 * STR;      // [64][72]
    float* sP = sV + 64 * STR;      // [128][72]

    const int bh = blockIdx.y;
    const int b = bh >> 3, h = bh & 7;
    const int q0 = blockIdx.x * 128;
    const int tid = threadIdx.x;
    const int warp = tid >> 5, lane = tid & 31;
    const int gid = lane >> 2, tig = lane & 3;
    const int qw = warp * 16;

    const float* qbase = g_qkv + (size_t)b * SS * N3 + h * (3 * DH);

    #pragma unroll
    for (int it = 0; it < 8; it++) {
        int idx = tid + it * 256;
        int i = idx >> 4, d4 = (idx & 15) << 2;
        float4 v = *(const float4*)&qbase[(size_t)(q0 + i) * N3 + d4];
        v.x *= ATT_SCALE; v.y *= ATT_SCALE; v.z *= ATT_SCALE; v.w *= ATT_SCALE;
        *(float4*)&sQ[i * STR + d4] = tf32r4(v);
    }

    float m_i0 = -1e30f, m_i1 = -1e30f, l_i0 = 0.f, l_i1 = 0.f;
    float o[8][4] = {};

    float4 kreg[4], vreg[4];
    #pragma unroll
    for (int it = 0; it < 4; it++) {
        int idx = tid + it * 256;
        int j = idx >> 4, c4 = (idx & 15) << 2;
        const float* row = &qbase[(size_t)j * N3];
        kreg[it] = *(const float4*)&row[DH + c4];
        vreg[it] = *(const float4*)&row[2 * DH + c4];
    }

    for (int kt = 0; kt < 16; kt++) {
        __syncthreads();
        #pragma unroll
        for (int it = 0; it < 4; it++) {
            int idx = tid + it * 256;
            int j = idx >> 4, c4 = (idx & 15) << 2;
            *(float4*)&sK[j * STR + c4] = tf32r4(kreg[it]);
            *(float4*)&sV[j * STR + c4] = tf32r4(vreg[it]);
        }
        __syncthreads();

        if (kt + 1 < 16) {
            const int k0n = (kt + 1) * 64;
            #pragma unroll
            for (int it = 0; it < 4; it++) {
                int idx = tid + it * 256;
                int j = idx >> 4, c4 = (idx & 15) << 2;
                const float* row = &qbase[(size_t)(k0n + j) * N3];
                kreg[it] = *(const float4*)&row[DH + c4];
                vreg[it] = *(const float4*)&row[2 * DH + c4];
            }
        }

        float sf[8][4] = {};
        #pragma unroll
        for (int ks = 0; ks < 64; ks += 8) {
            float afr[4];
            afr[0] = sQ[(qw + gid) * STR + ks + tig];
            afr[1] = sQ[(qw + gid + 8) * STR + ks + tig];
            afr[2] = sQ[(qw + gid) * STR + ks + tig + 4];
            afr[3] = sQ[(qw + gid + 8) * STR + ks + tig + 4];
            #pragma unroll
            for (int nf = 0; nf < 8; nf++) {
                float bfr[2];
                bfr[0] = sK[(nf * 8 + gid) * STR + ks + tig];
                bfr[1] = sK[(nf * 8 + gid) * STR + ks + tig + 4];
                mma_tf32(sf[nf], afr, bfr);
            }
        }

        {
            float mx0 = -1e30f, mx1 = -1e30f;
            #pragma unroll
            for (int nf = 0; nf < 8; nf++) {
                mx0 = fmaxf(mx0, fmaxf(sf[nf][0], sf[nf][1]));
                mx1 = fmaxf(mx1, fmaxf(sf[nf][2], sf[nf][3]));
            }
            mx0 = fmaxf(mx0, __shfl_xor_sync(0xffffffffu, mx0, 1));
            mx0 = fmaxf(mx0, __shfl_xor_sync(0xffffffffu, mx0, 2));
            mx1 = fmaxf(mx1, __shfl_xor_sync(0xffffffffu, mx1, 1));
            mx1 = fmaxf(mx1, __shfl_xor_sync(0xffffffffu, mx1, 2));
            float mn0 = fmaxf(m_i0, mx0);
            float mn1 = fmaxf(m_i1, mx1);
            float rs0 = 0.f, rs1 = 0.f;
            float* p0 = &sP[(qw + gid) * STR + 2 * tig];
            float* p1 = &sP[(qw + gid + 8) * STR + 2 * tig];
            #pragma unroll
            for (int nf = 0; nf < 8; nf++) {
                float e00 = __expf(sf[nf][0] - mn0);
                float e01 = __expf(sf[nf][1] - mn0);
                float e10 = __expf(sf[nf][2] - mn1);
                float e11 = __expf(sf[nf][3] - mn1);
                rs0 += e00 + e01;
                rs1 += e10 + e11;
                *(float2*)&p0[nf * 8] = make_float2(tf32r(e00), tf32r(e01));
                *(float2*)&p1[nf * 8] = make_float2(tf32r(e10), tf32r(e11));
            }
            rs0 += __shfl_xor_sync(0xffffffffu, rs0, 1);
            rs0 += __shfl_xor_sync(0xffffffffu, rs0, 2);
            rs1 += __shfl_xor_sync(0xffffffffu, rs1, 1);
            rs1 += __shfl_xor_sync(0xffffffffu, rs1, 2);
            float a0 = __expf(m_i0 - mn0);
            float a1 = __expf(m_i1 - mn1);
            l_i0 = l_i0 * a0 + rs0;  m_i0 = mn0;
            l_i1 = l_i1 * a1 + rs1;  m_i1 = mn1;
            #pragma unroll
            for (int nf = 0; nf < 8; nf++) {
                o[nf][0] *= a0; o[nf][1] *= a0;
                o[nf][2] *= a1; o[nf][3] *= a1;
            }
        }
        __syncwarp();

        #pragma unroll
        for (int ks = 0; ks < 64; ks += 8) {
            float afr[4];
            afr[0] = sP[(qw + gid) * STR + ks + tig];
            afr[1] = sP[(qw + gid + 8) * STR + ks + tig];
            afr[2] = sP[(qw + gid) * STR + ks + tig + 4];
            afr[3] = sP[(qw + gid + 8) * STR + ks + tig + 4];
            #pragma unroll
            for (int nf = 0; nf < 8; nf++) {
                float bfr[2];
                bfr[0] = sV[(ks + tig) * STR + nf * 8 + gid];
                bfr[1] = sV[(ks + tig + 4) * STR + nf * 8 + gid];
                mma_tf32(o[nf], afr, bfr);
            }
        }
    }

    const float inv0 = 1.f / l_i0;
    const float inv1 = 1.f / l_i1;
    float* rbase = g_res + ((size_t)b * SS + q0) * INNER + h * DH;
    #pragma unroll
    for (int nf = 0; nf < 8; nf++) {
        const int col = nf * 8 + 2 * tig;
        *(float2*)&rbase[(size_t)(qw + gid) * INNER + col] =
            make_float2(o[nf][0] * inv0, o[nf][1] * inv0);
        *(float2*)&rbase[(size_t)(qw + gid + 8) * INNER + col] =
            make_float2(o[nf][2] * inv1, o[nf][3] * inv1);
    }
}

// ---------------------------------------------------------------------------
// Kernel 3: out = res @ W_out + b_out + x.  bf16 m16n8k16, double-buffered.
// A = W_out[k][c] (transpose-packed), B = res[s][k] (k-contiguous: direct).
// ---------------------------------------------------------------------------
__global__ __launch_bounds__(256, 2) void out_gemm_k(
    const float* __restrict__ x, const float* __restrict__ Wo,
    const float* __restrict__ bo, float* __restrict__ out)
{
    __shared__ unsigned sAh[2][128 * PITCH];   // [c][kp]
    __shared__ unsigned sBh[2][128 * PITCH];   // [s][kp]
    const int s0 = blockIdx.x * 128;
    const int c0 = blockIdx.y * 128;
    const int b  = blockIdx.z;
    const int tid = threadIdx.x;
    const int warp = tid >> 5, lane = tid & 31;
    const int wm = warp & 1, wn = warp >> 1;
    const int gid = lane >> 2, tig = lane & 3;
    const int lr = tid & 127, hf = tid >> 7;

    float va[8];
    float4 vb0, vb1;
    #pragma unroll
    for (int kk = 0; kk < 8; kk++)
        va[kk] = Wo[(size_t)(hf * 8 + kk) * CC + c0 + lr];
    {
        const size_t brow = ((size_t)(b * SS + s0 + lr)) * INNER + hf * 8;
        vb0 = *(const float4*)&g_res[brow];
        vb1 = *(const float4*)&g_res[brow + 4];
    }
    {
        uint4 ua = make_uint4(bfpack(va[0], va[1]), bfpack(va[2], va[3]),
                              bfpack(va[4], va[5]), bfpack(va[6], va[7]));
        uint4 ub = make_uint4(bfpack(vb0.x, vb0.y), bfpack(vb0.z, vb0.w),
                              bfpack(vb1.x, vb1.y), bfpack(vb1.z, vb1.w));
        *(uint4*)&sAh[0][lr * PITCH + hf * 4] = ua;
        *(uint4*)&sBh[0][lr * PITCH + hf * 4] = ub;
    }
    __syncthreads();

    float acc[4][4][4] = {};

    for (int k0 = 0; k0 < INNER; k0 += 16) {
        const int buf = (k0 >> 4) & 1;
        const bool more = (k0 + 16) < INNER;
        if (more) {
            #pragma unroll
            for (int kk = 0; kk < 8; kk++)
                va[kk] = Wo[(size_t)(k0 + 16 + hf * 8 + kk) * CC + c0 + lr];
            const size_t brow = ((size_t)(b * SS + s0 + lr)) * INNER + k0 + 16 + hf * 8;
            vb0 = *(const float4*)&g_res[brow];
            vb1 = *(const float4*)&g_res[brow + 4];
        }
        unsigned afr[4][4], bfr[4][2];
        #pragma unroll
        for (int mf = 0; mf < 4; mf++) {
            const int m = wm * 64 + mf * 16;
            afr[mf][0] = sAh[buf][(m + gid) * PITCH + tig];
            afr[mf][1] = sAh[buf][(m + gid + 8) * PITCH + tig];
            afr[mf][2] = sAh[buf][(m + gid) * PITCH + tig + 4];
            afr[mf][3] = sAh[buf][(m + gid + 8) * PITCH + tig + 4];
        }
        #pragma unroll
        for (int nf = 0; nf < 4; nf++) {
            const int n = wn * 32 + nf * 8;
            bfr[nf][0] = sBh[buf][(n + gid) * PITCH + tig];
            bfr[nf][1] = sBh[buf][(n + gid) * PITCH + tig + 4];
        }
        #pragma unroll
        for (int mf = 0; mf < 4; mf++)
            #pragma unroll
            for (int nf = 0; nf < 4; nf++)
                mma_bf16(acc[mf][nf], afr[mf], bfr[nf]);
        if (more) {
            const int nb = buf ^ 1;
            uint4 ua = make_uint4(bfpack(va[0], va[1]), bfpack(va[2], va[3]),
                                  bfpack(va[4], va[5]), bfpack(va[6], va[7]));
            uint4 ub = make_uint4(bfpack(vb0.x, vb0.y), bfpack(vb0.z, vb0.w),
                                  bfpack(vb1.x, vb1.y), bfpack(vb1.z, vb1.w));
            __syncthreads();
            *(uint4*)&sAh[nb][lr * PITCH + hf * 4] = ua;
            *(uint4*)&sBh[nb][lr * PITCH + hf * 4] = ub;
            __syncthreads();
        }
    }

    #pragma unroll
    for (int mf = 0; mf < 4; mf++) {
        const int ca = c0 + wm * 64 + mf * 16 + gid;
        const int cb = ca + 8;
        const float biasa = bo[ca];
        const float biasb = bo[cb];
        #pragma unroll
        for (int nf = 0; nf < 4; nf++) {
            const int s = s0 + wn * 32 + nf * 8 + tig * 2;
            const size_t basea = ((size_t)(b * CC + ca)) * SS + s;
            const size_t baseb = ((size_t)(b * CC + cb)) * SS + s;
            float2 xva = *(const float2*)&x[basea];
            float2 xvb = *(const float2*)&x[baseb];
            float2 oa = make_float2(acc[mf][nf][0] + biasa + xva.x,
                                    acc[mf][nf][1] + biasa + xva.y);
            float2 ob = make_float2(acc[mf][nf][2] + biasb + xvb.x,
                                    acc[mf][nf][3] + biasb + xvb.y);
            *(float2*)&out[basea] = oa;
            *(float2*)&out[baseb] = ob;
        }
    }
}

// ---------------------------------------------------------------------------
extern "C" void kernel_launch(void* const* d_in, const int* in_sizes, int n_in,
                              void* d_out, int out_size)
{
    const float* x  = (const float*)d_in[0];
    const float* Wp = (const float*)d_in[1];
    const float* bp = (const float*)d_in[2];
    const float* Wo = (const float*)d_in[3];
    const float* bo = (const float*)d_in[4];
    float* out = (float*)d_out;

    const int attn_smem = (128 + 64 + 64 + 128) * STR * (int)sizeof(float); // 110592
    cudaFuncSetAttribute(attn_k, cudaFuncAttributeMaxDynamicSharedMemorySize,
                         attn_smem);

    dim3 g1(N3 / 128, (BB * SS) / 128);        // 12 x 128
    qkv_gemm_k<<<g1, 256>>>(x, Wp, bp);

    dim3 g2(SS / 128, BB * HEADS);             // 8 x 128
    attn_k<<<g2, 256, attn_smem>>>();

    dim3 g3(SS / 128, CC / 128, BB);           // 8 x 4 x 16
    out_gemm_k<<<g3, 256>>>(x, Wo, bo, out);
}